// round 11
// baseline (speedup 1.0000x reference)
#include <cuda_runtime.h>
#include <cuda_bf16.h>

#define Nn 100000
#define Ee 600000
#define Dd 128
#define Gg 256
#define EPSV 1e-5f

typedef unsigned long long ull;
typedef unsigned int uint32;

// ---------------- scratch (device globals; no allocation allowed) ----------------
__device__ __align__(16) float d_h[Nn * Dd];     // normed features (GEMM input + gather source)
__device__ __align__(16) float d_agg[Nn * Dd];   // segment-max result
__device__ __align__(16) float d_y[Nn * Dd];     // relu(x + sage) pre-norm2
__device__ __align__(16) float d_s1[Gg * Dd], d_q1[Gg * Dd];
__device__ __align__(16) float d_s2[Gg * Dd], d_q2[Gg * Dd];
__device__ __align__(16) float d_A1[Gg * Dd], d_C1[Gg * Dd];
__device__ __align__(16) float d_A2[Gg * Dd], d_C2[Gg * Dd];
__device__ float d_cnt[Gg];
__device__ int d_deg[Nn], d_start[Nn], d_cur[Nn], d_srcs[Ee];
__device__ int d_bsum[128];

// ---------------- zero scratch ----------------
__global__ void zeroKernel() {
    int i = blockIdx.x * blockDim.x + threadIdx.x;
    int stride = gridDim.x * blockDim.x;
    for (int j = i; j < Gg * Dd; j += stride) { d_s1[j] = 0.f; d_q1[j] = 0.f; d_s2[j] = 0.f; d_q2[j] = 0.f; }
    for (int j = i; j < Gg; j += stride) d_cnt[j] = 0.f;
    for (int j = i; j < Nn; j += stride) d_deg[j] = 0;
}

// ---------------- per-graph moments, pass 0 only (batch SORTED int32) ----------------
__global__ void momentsKernel(const float* __restrict__ x, const int* __restrict__ batch) {
    int lane = threadIdx.x;                       // 0..31 -> dims lane*4..lane*4+3
    int r0 = blockIdx.x * 256 + threadIdx.y * 32; // this stream's first row
    float4 a = make_float4(0.f, 0.f, 0.f, 0.f);
    float4 q = make_float4(0.f, 0.f, 0.f, 0.f);
    float c = 0.f;
    int curg = -1;

#define FLUSH_MOM()                                                             \
    {                                                                           \
        int base = curg * Dd + lane * 4;                                        \
        atomicAdd(&d_s1[base + 0], a.x); atomicAdd(&d_s1[base + 1], a.y);       \
        atomicAdd(&d_s1[base + 2], a.z); atomicAdd(&d_s1[base + 3], a.w);       \
        atomicAdd(&d_q1[base + 0], q.x); atomicAdd(&d_q1[base + 1], q.y);       \
        atomicAdd(&d_q1[base + 2], q.z); atomicAdd(&d_q1[base + 3], q.w);       \
        if (lane == 0) atomicAdd(&d_cnt[curg], c);                              \
    }

    for (int i = 0; i < 32; i++) {
        int r = r0 + i;
        if (r >= Nn) break;
        int g = __ldg(&batch[r]);
        if (g != curg) {
            if (curg >= 0) FLUSH_MOM();
            curg = g;
            a = make_float4(0.f, 0.f, 0.f, 0.f);
            q = make_float4(0.f, 0.f, 0.f, 0.f);
            c = 0.f;
        }
        float4 v = ((const float4*)x)[r * 32 + lane];
        a.x += v.x; a.y += v.y; a.z += v.z; a.w += v.w;
        q.x += v.x * v.x; q.y += v.y * v.y; q.z += v.z * v.z; q.w += v.w * v.w;
        c += 1.f;
    }
    if (curg >= 0) FLUSH_MOM();
#undef FLUSH_MOM
}

// ---------------- fold moments into affine (h = A*x + C) ----------------
__global__ void statsKernel(const float* __restrict__ w, const float* __restrict__ b,
                            const float* __restrict__ ms, int pass) {
    const float* sum = pass ? d_s2 : d_s1;
    const float* sq = pass ? d_q2 : d_q1;
    float* A = pass ? d_A2 : d_A1;
    float* C = pass ? d_C2 : d_C1;
    int i = blockIdx.x * blockDim.x + threadIdx.x;
    if (i >= Gg * Dd) return;
    int g = i >> 7, dch = i & 127;
    float cnt = fmaxf(d_cnt[g], 1.f);
    float mean = sum[i] / cnt;
    float ex2 = sq[i] / cnt;
    float m = ms[dch];
    float var = ex2 - (2.f * m - m * m) * mean * mean;
    float rstd = rsqrtf(var + EPSV);
    float aa = w[dch] * rstd;
    A[i] = aa;
    C[i] = b[dch] - mean * m * aa;
}

// ---------------- apply affine per node ----------------
__global__ void affineKernel(const float* __restrict__ xin, const int* __restrict__ batch,
                             float* __restrict__ dout, int pass) {
    const float* in = pass ? (const float*)d_y : xin;
    float* out = pass ? dout : (float*)d_h;
    const float* A = pass ? d_A2 : d_A1;
    const float* C = pass ? d_C2 : d_C1;
    int i = blockIdx.x * blockDim.x + threadIdx.x;  // float4 index
    if (i >= Nn * 32) return;
    int r = i >> 5, col = i & 31;
    int g = __ldg(&batch[r]);
    float4 v = ((const float4*)in)[i];
    float4 a = ((const float4*)A)[g * 32 + col];
    float4 c = ((const float4*)C)[g * 32 + col];
    float4 o;
    o.x = fmaf(a.x, v.x, c.x); o.y = fmaf(a.y, v.y, c.y);
    o.z = fmaf(a.z, v.z, c.z); o.w = fmaf(a.w, v.w, c.w);
    ((float4*)out)[i] = o;
}

// ---------------- CSR build: degree -> scan -> scatter ----------------
__global__ void degreeKernel(const int* __restrict__ ei) {
    int i = blockIdx.x * blockDim.x + threadIdx.x;
    if (i < Ee) atomicAdd(&d_deg[ei[Ee + i]], 1);
}

__global__ void scanBlocks() {  // 98 blocks x 1024 threads, exclusive scan within block
    __shared__ int wt[32];
    int i = blockIdx.x * 1024 + threadIdx.x;
    int v = (i < Nn) ? d_deg[i] : 0;
    int lane = threadIdx.x & 31, wd = threadIdx.x >> 5;
    int inc = v;
#pragma unroll
    for (int o = 1; o < 32; o <<= 1) {
        int t = __shfl_up_sync(0xffffffffu, inc, o);
        if (lane >= o) inc += t;
    }
    if (lane == 31) wt[wd] = inc;
    __syncthreads();
    if (wd == 0) {
        int t = wt[lane];
#pragma unroll
        for (int o = 1; o < 32; o <<= 1) {
            int u = __shfl_up_sync(0xffffffffu, t, o);
            if (lane >= o) t += u;
        }
        wt[lane] = t;
    }
    __syncthreads();
    int base = (wd > 0) ? wt[wd - 1] : 0;
    if (i < Nn) d_start[i] = base + inc - v;
    if (threadIdx.x == 1023) d_bsum[blockIdx.x] = base + inc;
}

__global__ void scanBsums() {  // 1 block, 128 threads; 98 valid entries -> exclusive
    __shared__ int s[128];
    int t = threadIdx.x;
    int v = (t < 98) ? d_bsum[t] : 0;
    s[t] = v;
    __syncthreads();
    for (int o = 1; o < 128; o <<= 1) {
        int u = (t >= o) ? s[t - o] : 0;
        __syncthreads();
        s[t] += u;
        __syncthreads();
    }
    if (t < 98) d_bsum[t] = s[t] - v;
}

__global__ void fixupKernel() {
    int i = blockIdx.x * blockDim.x + threadIdx.x;
    if (i < Nn) {
        int st = d_start[i] + d_bsum[i >> 10];
        d_start[i] = st;
        d_cur[i] = st;
    }
}

__global__ void scatterKernel(const int* __restrict__ ei) {
    int i = blockIdx.x * blockDim.x + threadIdx.x;
    if (i < Ee) {
        int dst = ei[Ee + i];
        int p = atomicAdd(&d_cur[dst], 1);
        d_srcs[p] = ei[i];
    }
}

// ---------------- segment-max aggregation: one warp per node ----------------
__global__ void aggKernel() {
    int w = (blockIdx.x * blockDim.x + threadIdx.x) >> 5;
    int lane = threadIdx.x & 31;
    if (w >= Nn) return;
    int s = d_start[w], dg = d_deg[w];
    float4 acc = make_float4(-3.0e38f, -3.0e38f, -3.0e38f, -3.0e38f);
    for (int base = 0; base < dg; base += 32) {
        int rem = dg - base;
        if (rem > 32) rem = 32;
        int sc = (lane < rem) ? d_srcs[s + base + lane] : 0;
        for (int j = 0; j < rem; j++) {
            int scj = __shfl_sync(0xffffffffu, sc, j);
            float4 v = ((const float4*)d_h)[scj * 32 + lane];
            acc.x = fmaxf(acc.x, v.x); acc.y = fmaxf(acc.y, v.y);
            acc.z = fmaxf(acc.z, v.z); acc.w = fmaxf(acc.w, v.w);
        }
    }
    if (dg == 0) acc = make_float4(0.f, 0.f, 0.f, 0.f);  // PyG: empty segments -> 0
    ((float4*)d_agg)[w * 32 + lane] = acc;
}

// ================= tensor-core GEMM (bf16 split, HMMA mma.sync) — R9 structure =================
// y = relu(x + agg@wl^T + b_l + h@wr^T) as ONE bf16 GEMM with K2 = 768 (3 segments).
// NEW: epilogue ALSO accumulates GraphNorm-2 moments (sum, sum^2) into d_s2/d_q2,
// eliminating the 51 MB momentsKernel pass-1. Block rows are consecutive and batch
// is sorted -> per-block graph span is tiny; smem-reduce (<=8 graphs) then one
// global atomicAdd per (graph,dim); fallback to direct atomics if span > 8.

__device__ __forceinline__ uint32 packbf(float lo, float hi) {
    uint32 r;
    asm("cvt.rn.bf16x2.f32 %0, %1, %2;" : "=r"(r) : "f"(hi), "f"(lo));
    return r;
}

__device__ __forceinline__ void mma16816(float* c, const uint32* a, const uint32* b) {
    asm volatile(
        "mma.sync.aligned.m16n8k16.row.col.f32.bf16.bf16.f32 "
        "{%0,%1,%2,%3}, {%4,%5,%6,%7}, {%8,%9}, {%0,%1,%2,%3};"
        : "+f"(c[0]), "+f"(c[1]), "+f"(c[2]), "+f"(c[3])
        : "r"(a[0]), "r"(a[1]), "r"(a[2]), "r"(a[3]), "r"(b[0]), "r"(b[1]));
}

#define MAXSPAN 8

__global__ __launch_bounds__(256) void gemmKernel(const float* __restrict__ wl,
                                                  const float* __restrict__ wr,
                                                  const float* __restrict__ bl,
                                                  const float* __restrict__ x,
                                                  const int* __restrict__ batch) {
    // aS: [m16 0..7][kstep 0..3][lane 0..31][4 u32]  -> 4096 u32 = 16 KB
    // bS: [kstep 0..3][n8 0..15][lane 0..31][2 u32]  -> 4096 u32 = 16 KB
    __shared__ __align__(16) uint32 aS[4096];
    __shared__ __align__(16) uint32 bS[4096];

    int tid = threadIdx.x;
    int lane = tid & 31, wid = tid >> 5;
    int warpM = wid >> 1, warpN = wid & 1;
    int r0 = blockIdx.x * 128;

    float acc[2][8][4];
#pragma unroll
    for (int mi = 0; mi < 2; mi++)
#pragma unroll
        for (int j = 0; j < 8; j++)
#pragma unroll
            for (int q = 0; q < 4; q++) acc[mi][j][q] = 0.f;

    for (int c = 0; c < 12; c++) {
        int seg = c >> 2;            // 0,1,2
        int ks0 = (c & 3) * 64;      // 0,64,128,192 within K=256
        int aLo = (seg == 2);
        int wLo = (seg == 1);
        const float* srcA = (ks0 < 128) ? (const float*)d_agg : (const float*)d_h;
        const float* srcW = (ks0 < 128) ? wl : wr;
        int koff = ks0 & 127;

        __syncthreads();  // previous chunk's compute done before refill

        // ---- fill A fragments (coalesced float2 gmem reads) ----
#pragma unroll
        for (int it = 0; it < 16; it++) {
            int idx = tid + it * 256;           // 0..4095 (row, k-pair)
            int row = idx >> 5, kp = idx & 31;
            int r = r0 + row;
            float2 v = make_float2(0.f, 0.f);
            if (r < Nn) v = *(const float2*)(srcA + r * 128 + koff + kp * 2);
            float h0 = __bfloat162float(__float2bfloat16(v.x));
            float h1 = __bfloat162float(__float2bfloat16(v.y));
            uint32 pk = aLo ? packbf(v.x - h0, v.y - h1) : packbf(v.x, v.y);
            int m16 = row >> 4, rr = row & 15;
            int kstep = kp >> 3, p = kp & 7;
            int t = (rr & 7) * 4 + (p & 3);
            int reg = (rr >> 3) + ((p >> 2) << 1);
            aS[((m16 * 4 + kstep) * 32 + t) * 4 + reg] = pk;
        }
        // ---- fill B fragments ----
#pragma unroll
        for (int it = 0; it < 16; it++) {
            int idx = tid + it * 256;           // (n, k-pair)
            int n = idx >> 5, kp = idx & 31;
            float2 v = *(const float2*)(srcW + n * 128 + koff + kp * 2);
            float h0 = __bfloat162float(__float2bfloat16(v.x));
            float h1 = __bfloat162float(__float2bfloat16(v.y));
            uint32 pk = wLo ? packbf(v.x - h0, v.y - h1) : packbf(v.x, v.y);
            int kstep = kp >> 3, p = kp & 7;
            int n8 = n >> 3, nn = n & 7;
            int t = nn * 4 + (p & 3);
            int reg = p >> 2;
            bS[((kstep * 16 + n8) * 32 + t) * 2 + reg] = pk;
        }
        __syncthreads();

        // ---- mainloop: 4 ksteps x 16 HMMA per warp ----
#pragma unroll
        for (int kstep = 0; kstep < 4; kstep++) {
            uint32 a[2][4];
#pragma unroll
            for (int mi = 0; mi < 2; mi++) {
                int m16 = warpM * 2 + mi;
                *(uint4*)a[mi] = *(const uint4*)&aS[((m16 * 4 + kstep) * 32 + lane) * 4];
            }
#pragma unroll
            for (int j = 0; j < 8; j++) {
                uint32 b[2];
                *(uint2*)b = *(const uint2*)&bS[((kstep * 16 + warpN * 8 + j) * 32 + lane) * 2];
                mma16816(acc[0][j], a[0], b);
                mma16816(acc[1][j], a[1], b);
            }
        }
    }

    // ---- epilogue: bias + residual + relu -> d_y, fused GraphNorm-2 moments ----
    __syncthreads();                        // mainloop smem reads done; reuse aS
    float* sSum = (float*)aS;               // [MAXSPAN][128] = 4 KB
    float* sSq = sSum + MAXSPAN * 128;      // [MAXSPAN][128] = 4 KB (fits in aS 16 KB)

    int rLast = r0 + 127; if (rLast >= Nn) rLast = Nn - 1;
    int g0 = __ldg(&batch[r0]);
    int span = __ldg(&batch[rLast]) - g0 + 1;
    bool useSmem = (span <= MAXSPAN);
    if (useSmem) {
        for (int i = tid; i < MAXSPAN * 128; i += 256) { sSum[i] = 0.f; sSq[i] = 0.f; }
    }
    __syncthreads();

#pragma unroll
    for (int mi = 0; mi < 2; mi++) {
        int rbase = r0 + warpM * 32 + mi * 16 + (lane >> 2);
#pragma unroll
        for (int half = 0; half < 2; half++) {
            int r = rbase + half * 8;
            if (r >= Nn) continue;
            int gi = __ldg(&batch[r]) - g0;
            float2 xrow0, xrow1;
#pragma unroll
            for (int j = 0; j < 8; j++) {
                int nc = warpN * 64 + j * 8 + (lane & 3) * 2;
                float b0 = __ldg(&bl[nc]), b1 = __ldg(&bl[nc + 1]);
                float2 xv = *(const float2*)(x + r * 128 + nc);
                float v0 = fmaxf(acc[mi][j][half * 2 + 0] + b0 + xv.x, 0.f);
                float v1 = fmaxf(acc[mi][j][half * 2 + 1] + b1 + xv.y, 0.f);
                float2 o = make_float2(v0, v1);
                *(float2*)(d_y + r * 128 + nc) = o;
                if (useSmem) {
                    atomicAdd(&sSum[gi * 128 + nc], v0);
                    atomicAdd(&sSum[gi * 128 + nc + 1], v1);
                    atomicAdd(&sSq[gi * 128 + nc], v0 * v0);
                    atomicAdd(&sSq[gi * 128 + nc + 1], v1 * v1);
                } else {
                    int gb = (gi + g0) * 128 + nc;
                    atomicAdd(&d_s2[gb], v0); atomicAdd(&d_s2[gb + 1], v1);
                    atomicAdd(&d_q2[gb], v0 * v0); atomicAdd(&d_q2[gb + 1], v1 * v1);
                }
            }
            (void)xrow0; (void)xrow1;
        }
    }
    __syncthreads();

    if (useSmem) {
        for (int i = tid; i < span * 128; i += 256) {
            int gb = (g0 + (i >> 7)) * 128 + (i & 127);
            float sv = sSum[i], qv = sSq[i];
            if (sv != 0.f || qv != 0.f) {
                atomicAdd(&d_s2[gb], sv);
                atomicAdd(&d_q2[gb], qv);
            }
        }
    }
}

// ---------------- launch (capture-safe: kernel launches ONLY) ----------------
extern "C" void kernel_launch(void* const* d_in, const int* in_sizes, int n_in,
                              void* d_out, int out_size) {
    const float* x = (const float*)d_in[0];
    const int* ei = (const int*)d_in[1];      // int32 (JAX x64 disabled)
    const int* batch = (const int*)d_in[2];   // int32
    const float* n1w = (const float*)d_in[3];
    const float* n1b = (const float*)d_in[4];
    const float* n1ms = (const float*)d_in[5];
    const float* n2w = (const float*)d_in[6];
    const float* n2b = (const float*)d_in[7];
    const float* n2ms = (const float*)d_in[8];
    const float* wl = (const float*)d_in[9];
    const float* bl = (const float*)d_in[10];
    const float* wr = (const float*)d_in[11];
    float* out = (float*)d_out;

    zeroKernel<<<512, 256>>>();
    // ---- GraphNorm 1: x -> d_h ----
    momentsKernel<<<391, dim3(32, 8)>>>(x, batch);
    statsKernel<<<128, 256>>>(n1w, n1b, n1ms, 0);
    affineKernel<<<12500, 256>>>(x, batch, out, 0);   // pass 0 writes d_h internally
    // ---- CSR build (by dst) ----
    degreeKernel<<<2344, 256>>>(ei);
    scanBlocks<<<98, 1024>>>();
    scanBsums<<<1, 128>>>();
    fixupKernel<<<391, 256>>>();
    scatterKernel<<<2344, 256>>>(ei);
    // ---- segment-max aggregation ----
    aggKernel<<<12500, 256>>>();
    // ---- fused SAGE GEMMs + bias + residual + relu -> d_y, + GraphNorm-2 moments ----
    gemmKernel<<<782, 256>>>(wl, wr, bl, x, batch);
    // ---- GraphNorm 2 finish: stats + affine (d_y -> out) ----
    statsKernel<<<128, 256>>>(n2w, n2b, n2ms, 1);
    affineKernel<<<12500, 256>>>(x, batch, out, 1);   // pass 1 reads d_y, writes out
}

// round 13
// speedup vs baseline: 1.5054x; 1.5054x over previous
#include <cuda_runtime.h>
#include <cuda_bf16.h>

#define Nn 100000
#define Ee 600000
#define Dd 128
#define Gg 256
#define EPSV 1e-5f

typedef unsigned long long ull;
typedef unsigned int uint32;

// ---------------- scratch (device globals; no allocation allowed) ----------------
__device__ __align__(16) float d_h[Nn * Dd];       // normed features fp32 (gather source)
__device__ __align__(16) uint32 d_hH[Nn * 64];     // bf16x2-packed hi(h)
__device__ __align__(16) uint32 d_hL[Nn * 64];     // bf16x2-packed lo(h)
__device__ __align__(16) uint32 d_aggH[Nn * 64];   // bf16x2-packed hi(agg)
__device__ __align__(16) uint32 d_aggL[Nn * 64];   // bf16x2-packed lo(agg)
__device__ __align__(16) uint32 d_wH[256 * 64];    // bf16x2-packed hi(wl|wr)
__device__ __align__(16) uint32 d_wL[256 * 64];    // bf16x2-packed lo(wl|wr)
__device__ __align__(16) float d_y[Nn * Dd];       // relu(x + sage) pre-norm2
__device__ __align__(16) float d_s1[Gg * Dd], d_q1[Gg * Dd];
__device__ __align__(16) float d_s2[Gg * Dd], d_q2[Gg * Dd];
__device__ __align__(16) float d_A1[Gg * Dd], d_C1[Gg * Dd];
__device__ __align__(16) float d_A2[Gg * Dd], d_C2[Gg * Dd];
__device__ float d_cnt[Gg];
__device__ int d_deg[Nn], d_start[Nn], d_cur[Nn], d_srcs[Ee];
__device__ int d_bsum[128];

// ---------------- helpers ----------------
__device__ __forceinline__ uint32 packbf(float lo, float hi) {
    uint32 r;
    asm("cvt.rn.bf16x2.f32 %0, %1, %2;" : "=r"(r) : "f"(hi), "f"(lo));
    return r;
}
// pack a pair (a=even k, b=odd k) into hi/lo bf16x2 words
__device__ __forceinline__ void packHL(float a, float b, uint32& H, uint32& L) {
    float ha = __bfloat162float(__float2bfloat16(a));
    float hb = __bfloat162float(__float2bfloat16(b));
    H = packbf(a, b);
    L = packbf(a - ha, b - hb);
}

// ---------------- zero scratch ----------------
__global__ void zeroKernel() {
    int i = blockIdx.x * blockDim.x + threadIdx.x;
    int stride = gridDim.x * blockDim.x;
    for (int j = i; j < Gg * Dd; j += stride) { d_s1[j] = 0.f; d_q1[j] = 0.f; d_s2[j] = 0.f; d_q2[j] = 0.f; }
    for (int j = i; j < Gg; j += stride) d_cnt[j] = 0.f;
    for (int j = i; j < Nn; j += stride) d_deg[j] = 0;
}

// ---------------- weight hi/lo pre-pack: rows 0..127 = wl, 128..255 = wr ----------------
__global__ void wprepKernel(const float* __restrict__ wl, const float* __restrict__ wr) {
    int i = blockIdx.x * blockDim.x + threadIdx.x;   // (n 0..255, cp 0..63)
    if (i >= 256 * 64) return;
    int n = i >> 6, cp = i & 63;
    const float* W = (n < 128) ? wl : wr;
    float2 v = *(const float2*)(W + (n & 127) * 128 + cp * 2);
    uint32 H, L;
    packHL(v.x, v.y, H, L);
    d_wH[i] = H;
    d_wL[i] = L;
}

// ---------------- per-graph moments (batch SORTED int32; register-accumulate, boundary flush)
__global__ void momentsKernel(const float* __restrict__ xin, const int* __restrict__ batch,
                              int pass) {
    const float* x = pass ? (const float*)d_y : xin;
    float* sum = pass ? d_s2 : d_s1;
    float* sq = pass ? d_q2 : d_q1;
    int doCnt = (pass == 0);
    int lane = threadIdx.x;                       // 0..31 -> dims lane*4..lane*4+3
    int r0 = blockIdx.x * 256 + threadIdx.y * 32; // this stream's first row
    float4 a = make_float4(0.f, 0.f, 0.f, 0.f);
    float4 q = make_float4(0.f, 0.f, 0.f, 0.f);
    float c = 0.f;
    int curg = -1;

#define FLUSH_MOM()                                                             \
    {                                                                           \
        int base = curg * Dd + lane * 4;                                        \
        atomicAdd(&sum[base + 0], a.x); atomicAdd(&sum[base + 1], a.y);         \
        atomicAdd(&sum[base + 2], a.z); atomicAdd(&sum[base + 3], a.w);         \
        atomicAdd(&sq[base + 0], q.x);  atomicAdd(&sq[base + 1], q.y);          \
        atomicAdd(&sq[base + 2], q.z);  atomicAdd(&sq[base + 3], q.w);          \
        if (doCnt && lane == 0) atomicAdd(&d_cnt[curg], c);                     \
    }

    for (int i = 0; i < 32; i++) {
        int r = r0 + i;
        if (r >= Nn) break;
        int g = __ldg(&batch[r]);
        if (g != curg) {
            if (curg >= 0) FLUSH_MOM();
            curg = g;
            a = make_float4(0.f, 0.f, 0.f, 0.f);
            q = make_float4(0.f, 0.f, 0.f, 0.f);
            c = 0.f;
        }
        float4 v = ((const float4*)x)[r * 32 + lane];
        a.x += v.x; a.y += v.y; a.z += v.z; a.w += v.w;
        q.x += v.x * v.x; q.y += v.y * v.y; q.z += v.z * v.z; q.w += v.w * v.w;
        c += 1.f;
    }
    if (curg >= 0) FLUSH_MOM();
#undef FLUSH_MOM
}

// ---------------- fold moments into affine (h = A*x + C) ----------------
__global__ void statsKernel(const float* __restrict__ w, const float* __restrict__ b,
                            const float* __restrict__ ms, int pass) {
    const float* sum = pass ? d_s2 : d_s1;
    const float* sq = pass ? d_q2 : d_q1;
    float* A = pass ? d_A2 : d_A1;
    float* C = pass ? d_C2 : d_C1;
    int i = blockIdx.x * blockDim.x + threadIdx.x;
    if (i >= Gg * Dd) return;
    int g = i >> 7, dch = i & 127;
    float cnt = fmaxf(d_cnt[g], 1.f);
    float mean = sum[i] / cnt;
    float ex2 = sq[i] / cnt;
    float m = ms[dch];
    float var = ex2 - (2.f * m - m * m) * mean * mean;
    float rstd = rsqrtf(var + EPSV);
    float aa = w[dch] * rstd;
    A[i] = aa;
    C[i] = b[dch] - mean * m * aa;
}

// ---------------- apply affine per node ----------------
// pass 0: in = x, out = d_h fp32 + d_hH/d_hL packed bf16. pass 1: in = d_y, out = dout.
__global__ void affineKernel(const float* __restrict__ xin, const int* __restrict__ batch,
                             float* __restrict__ dout, int pass) {
    const float* in = pass ? (const float*)d_y : xin;
    float* out = pass ? dout : (float*)d_h;
    const float* A = pass ? d_A2 : d_A1;
    const float* C = pass ? d_C2 : d_C1;
    int i = blockIdx.x * blockDim.x + threadIdx.x;  // float4 index
    if (i >= Nn * 32) return;
    int r = i >> 5, col = i & 31;
    int g = __ldg(&batch[r]);
    float4 v = ((const float4*)in)[i];
    float4 a = ((const float4*)A)[g * 32 + col];
    float4 c = ((const float4*)C)[g * 32 + col];
    float4 o;
    o.x = fmaf(a.x, v.x, c.x); o.y = fmaf(a.y, v.y, c.y);
    o.z = fmaf(a.z, v.z, c.z); o.w = fmaf(a.w, v.w, c.w);
    ((float4*)out)[i] = o;
    if (!pass) {
        uint32 H0, L0, H1, L1;
        packHL(o.x, o.y, H0, L0);
        packHL(o.z, o.w, H1, L1);
        int p = r * 64 + col * 2;   // 8B-aligned pair
        *(ull*)&d_hH[p] = ((ull)H1 << 32) | H0;
        *(ull*)&d_hL[p] = ((ull)L1 << 32) | L0;
    }
}

// ---------------- CSR build: degree -> scan -> scatter ----------------
__global__ void degreeKernel(const int* __restrict__ ei) {
    int i = blockIdx.x * blockDim.x + threadIdx.x;
    if (i < Ee) atomicAdd(&d_deg[ei[Ee + i]], 1);
}

__global__ void scanBlocks() {  // 98 blocks x 1024 threads, exclusive scan within block
    __shared__ int wt[32];
    int i = blockIdx.x * 1024 + threadIdx.x;
    int v = (i < Nn) ? d_deg[i] : 0;
    int lane = threadIdx.x & 31, wd = threadIdx.x >> 5;
    int inc = v;
#pragma unroll
    for (int o = 1; o < 32; o <<= 1) {
        int t = __shfl_up_sync(0xffffffffu, inc, o);
        if (lane >= o) inc += t;
    }
    if (lane == 31) wt[wd] = inc;
    __syncthreads();
    if (wd == 0) {
        int t = wt[lane];
#pragma unroll
        for (int o = 1; o < 32; o <<= 1) {
            int u = __shfl_up_sync(0xffffffffu, t, o);
            if (lane >= o) t += u;
        }
        wt[lane] = t;
    }
    __syncthreads();
    int base = (wd > 0) ? wt[wd - 1] : 0;
    if (i < Nn) d_start[i] = base + inc - v;
    if (threadIdx.x == 1023) d_bsum[blockIdx.x] = base + inc;
}

__global__ void scanBsums() {  // 1 block, 128 threads; 98 valid entries -> exclusive
    __shared__ int s[128];
    int t = threadIdx.x;
    int v = (t < 98) ? d_bsum[t] : 0;
    s[t] = v;
    __syncthreads();
    for (int o = 1; o < 128; o <<= 1) {
        int u = (t >= o) ? s[t - o] : 0;
        __syncthreads();
        s[t] += u;
        __syncthreads();
    }
    if (t < 98) d_bsum[t] = s[t] - v;
}

__global__ void fixupKernel() {
    int i = blockIdx.x * blockDim.x + threadIdx.x;
    if (i < Nn) {
        int st = d_start[i] + d_bsum[i >> 10];
        d_start[i] = st;
        d_cur[i] = st;
    }
}

__global__ void scatterKernel(const int* __restrict__ ei) {
    int i = blockIdx.x * blockDim.x + threadIdx.x;
    if (i < Ee) {
        int dst = ei[Ee + i];
        int p = atomicAdd(&d_cur[dst], 1);
        d_srcs[p] = ei[i];
    }
}

// ---------------- segment-max aggregation: one warp per node ----------------
// Gathers fp32 h rows; emits packed bf16 hi/lo directly (same write volume as fp32).
__global__ void aggKernel() {
    int w = (blockIdx.x * blockDim.x + threadIdx.x) >> 5;
    int lane = threadIdx.x & 31;
    if (w >= Nn) return;
    int s = d_start[w], dg = d_deg[w];
    float4 acc = make_float4(-3.0e38f, -3.0e38f, -3.0e38f, -3.0e38f);
    for (int base = 0; base < dg; base += 32) {
        int rem = dg - base;
        if (rem > 32) rem = 32;
        int sc = (lane < rem) ? d_srcs[s + base + lane] : 0;
        for (int j = 0; j < rem; j++) {
            int scj = __shfl_sync(0xffffffffu, sc, j);
            float4 v = ((const float4*)d_h)[scj * 32 + lane];
            acc.x = fmaxf(acc.x, v.x); acc.y = fmaxf(acc.y, v.y);
            acc.z = fmaxf(acc.z, v.z); acc.w = fmaxf(acc.w, v.w);
        }
    }
    if (dg == 0) acc = make_float4(0.f, 0.f, 0.f, 0.f);  // PyG: empty segments -> 0
    uint32 H0, L0, H1, L1;
    packHL(acc.x, acc.y, H0, L0);
    packHL(acc.z, acc.w, H1, L1);
    int p = w * 64 + lane * 2;
    *(ull*)&d_aggH[p] = ((ull)H1 << 32) | H0;
    *(ull*)&d_aggL[p] = ((ull)L1 << 32) | L0;
}

// ================= tensor-core GEMM (bf16 split, HMMA mma.sync) — R9 mainloop =================
// y = relu(x + agg@wl^T + b_l + h@wr^T) as ONE bf16 GEMM with K2 = 768 (3 segments:
// hi*hi, hi*lo, lo*hi; lo*lo dropped ~2^-16). Operands are PRE-PACKED bf16x2 in gmem
// (d_aggH/L, d_hH/L, d_wH/L) -> fills are pure LDG.32 + permuted STS.32 (no cvt, half
// the L2 read traffic of R9). Mainloop/epilogue byte-identical to the 282us R9 kernel.

__device__ __forceinline__ void mma16816(float* c, const uint32* a, const uint32* b) {
    asm volatile(
        "mma.sync.aligned.m16n8k16.row.col.f32.bf16.bf16.f32 "
        "{%0,%1,%2,%3}, {%4,%5,%6,%7}, {%8,%9}, {%0,%1,%2,%3};"
        : "+f"(c[0]), "+f"(c[1]), "+f"(c[2]), "+f"(c[3])
        : "r"(a[0]), "r"(a[1]), "r"(a[2]), "r"(a[3]), "r"(b[0]), "r"(b[1]));
}

__global__ __launch_bounds__(256) void gemmKernel(const float* __restrict__ bl,
                                                  const float* __restrict__ x) {
    // aS: [m16 0..7][kstep 0..3][lane 0..31][4 u32]  -> 4096 u32 = 16 KB
    // bS: [kstep 0..3][n8 0..15][lane 0..31][2 u32]  -> 4096 u32 = 16 KB
    __shared__ __align__(16) uint32 aS[4096];
    __shared__ __align__(16) uint32 bS[4096];

    int tid = threadIdx.x;
    int lane = tid & 31, wid = tid >> 5;
    int warpM = wid >> 1, warpN = wid & 1;
    int r0 = blockIdx.x * 128;

    float acc[2][8][4];
#pragma unroll
    for (int mi = 0; mi < 2; mi++)
#pragma unroll
        for (int j = 0; j < 8; j++)
#pragma unroll
            for (int q = 0; q < 4; q++) acc[mi][j][q] = 0.f;

    for (int c = 0; c < 12; c++) {
        int seg = c >> 2;            // 0: hi*hi, 1: hi*lo, 2: lo*hi
        int ks0 = (c & 3) * 64;      // 0,64,128,192 within K=256
        const uint32* srcA = (seg == 2) ? ((ks0 < 128) ? d_aggL : d_hL)
                                        : ((ks0 < 128) ? d_aggH : d_hH);
        const uint32* srcW = (seg == 1) ? d_wL : d_wH;
        int kpoff = (ks0 & 127) >> 1;               // u32 (k-pair) offset within row of 64
        int wbase = (ks0 < 128) ? 0 : 128 * 64;     // wl rows 0..127, wr rows 128..255

        __syncthreads();  // previous chunk's compute done before refill

        // ---- fill A fragments (pure u32 loads, coalesced) ----
#pragma unroll
        for (int it = 0; it < 16; it++) {
            int idx = tid + it * 256;           // 0..4095 (row, k-pair)
            int row = idx >> 5, kp = idx & 31;
            int r = r0 + row;
            uint32 pk = (r < Nn) ? __ldg(&srcA[r * 64 + kpoff + kp]) : 0u;
            int m16 = row >> 4, rr = row & 15;
            int kstep = kp >> 3, p = kp & 7;
            int t = (rr & 7) * 4 + (p & 3);
            int reg = (rr >> 3) + ((p >> 2) << 1);
            aS[((m16 * 4 + kstep) * 32 + t) * 4 + reg] = pk;
        }
        // ---- fill B fragments ----
#pragma unroll
        for (int it = 0; it < 16; it++) {
            int idx = tid + it * 256;           // (n, k-pair)
            int n = idx >> 5, kp = idx & 31;
            uint32 pk = __ldg(&srcW[wbase + n * 64 + kpoff + kp]);
            int kstep = kp >> 3, p = kp & 7;
            int n8 = n >> 3, nn = n & 7;
            int t = nn * 4 + (p & 3);
            int reg = p >> 2;
            bS[((kstep * 16 + n8) * 32 + t) * 2 + reg] = pk;
        }
        __syncthreads();

        // ---- mainloop: 4 ksteps x 16 HMMA per warp ----
#pragma unroll
        for (int kstep = 0; kstep < 4; kstep++) {
            uint32 a[2][4];
#pragma unroll
            for (int mi = 0; mi < 2; mi++) {
                int m16 = warpM * 2 + mi;
                *(uint4*)a[mi] = *(const uint4*)&aS[((m16 * 4 + kstep) * 32 + lane) * 4];
            }
#pragma unroll
            for (int j = 0; j < 8; j++) {
                uint32 b[2];
                *(uint2*)b = *(const uint2*)&bS[((kstep * 16 + warpN * 8 + j) * 32 + lane) * 2];
                mma16816(acc[0][j], a[0], b);
                mma16816(acc[1][j], a[1], b);
            }
        }
    }

    // ---- epilogue: bias + residual + relu -> d_y ----
#pragma unroll
    for (int mi = 0; mi < 2; mi++) {
        int rbase = r0 + warpM * 32 + mi * 16 + (lane >> 2);
#pragma unroll
        for (int j = 0; j < 8; j++) {
            int nc = warpN * 64 + j * 8 + (lane & 3) * 2;
            float b0 = __ldg(&bl[nc]), b1 = __ldg(&bl[nc + 1]);
            int r = rbase;
            if (r < Nn) {
                float2 xv = *(const float2*)(x + r * 128 + nc);
                float2 o;
                o.x = fmaxf(acc[mi][j][0] + b0 + xv.x, 0.f);
                o.y = fmaxf(acc[mi][j][1] + b1 + xv.y, 0.f);
                *(float2*)(d_y + r * 128 + nc) = o;
            }
            r = rbase + 8;
            if (r < Nn) {
                float2 xv = *(const float2*)(x + r * 128 + nc);
                float2 o;
                o.x = fmaxf(acc[mi][j][2] + b0 + xv.x, 0.f);
                o.y = fmaxf(acc[mi][j][3] + b1 + xv.y, 0.f);
                *(float2*)(d_y + r * 128 + nc) = o;
            }
        }
    }
}

// ---------------- launch (capture-safe: kernel launches ONLY) ----------------
extern "C" void kernel_launch(void* const* d_in, const int* in_sizes, int n_in,
                              void* d_out, int out_size) {
    const float* x = (const float*)d_in[0];
    const int* ei = (const int*)d_in[1];      // int32 (JAX x64 disabled)
    const int* batch = (const int*)d_in[2];   // int32
    const float* n1w = (const float*)d_in[3];
    const float* n1b = (const float*)d_in[4];
    const float* n1ms = (const float*)d_in[5];
    const float* n2w = (const float*)d_in[6];
    const float* n2b = (const float*)d_in[7];
    const float* n2ms = (const float*)d_in[8];
    const float* wl = (const float*)d_in[9];
    const float* bl = (const float*)d_in[10];
    const float* wr = (const float*)d_in[11];
    float* out = (float*)d_out;

    zeroKernel<<<512, 256>>>();
    wprepKernel<<<64, 256>>>(wl, wr);
    // ---- GraphNorm 1: x -> d_h (fp32) + d_hH/d_hL (packed bf16) ----
    momentsKernel<<<391, dim3(32, 8)>>>(x, batch, 0);
    statsKernel<<<128, 256>>>(n1w, n1b, n1ms, 0);
    affineKernel<<<12500, 256>>>(x, batch, out, 0);
    // ---- CSR build (by dst) ----
    degreeKernel<<<2344, 256>>>(ei);
    scanBlocks<<<98, 1024>>>();
    scanBsums<<<1, 128>>>();
    fixupKernel<<<391, 256>>>();
    scatterKernel<<<2344, 256>>>(ei);
    // ---- segment-max aggregation -> d_aggH/d_aggL (packed bf16) ----
    aggKernel<<<12500, 256>>>();
    // ---- fused SAGE GEMMs + bias + residual + relu -> d_y (HMMA) ----
    gemmKernel<<<782, 256>>>(bl, x);
    // ---- GraphNorm 2: d_y -> out ----
    momentsKernel<<<391, dim3(32, 8)>>>(x, batch, 1); // pass 1 reads d_y internally
    statsKernel<<<128, 256>>>(n2w, n2b, n2ms, 1);
    affineKernel<<<12500, 256>>>(x, batch, out, 1);   // pass 1 reads d_y, writes out
}

// round 14
// speedup vs baseline: 1.5856x; 1.0533x over previous
#include <cuda_runtime.h>
#include <cuda_bf16.h>

#define Nn 100000
#define Ee 600000
#define Dd 128
#define Gg 256
#define EPSV 1e-5f

typedef unsigned long long ull;
typedef unsigned int uint32;

// ---------------- scratch (device globals; no allocation allowed) ----------------
__device__ __align__(16) uint32 d_hH[Nn * 64];     // bf16x2-packed hi(h)  (h fp32 dropped)
__device__ __align__(16) uint32 d_hL[Nn * 64];     // bf16x2-packed lo(h)
__device__ __align__(16) uint32 d_aggH[Nn * 64];   // bf16x2-packed hi(agg)
__device__ __align__(16) uint32 d_aggL[Nn * 64];   // bf16x2-packed lo(agg)
__device__ __align__(16) uint32 d_wH[256 * 64];    // bf16x2-packed hi(wl|wr)
__device__ __align__(16) uint32 d_wL[256 * 64];    // bf16x2-packed lo(wl|wr)
__device__ __align__(16) float d_y[Nn * Dd];       // relu(x + sage) pre-norm2
__device__ __align__(16) float d_s1[Gg * Dd], d_q1[Gg * Dd];
__device__ __align__(16) float d_s2[Gg * Dd], d_q2[Gg * Dd];
__device__ __align__(16) float d_A1[Gg * Dd], d_C1[Gg * Dd];
__device__ __align__(16) float d_A2[Gg * Dd], d_C2[Gg * Dd];
__device__ float d_cnt[Gg];
__device__ int d_deg[Nn], d_start[Nn], d_cur[Nn], d_srcs[Ee];
__device__ int d_bsum[128];

// ---------------- helpers ----------------
__device__ __forceinline__ uint32 packbf(float lo, float hi) {
    uint32 r;
    asm("cvt.rn.bf16x2.f32 %0, %1, %2;" : "=r"(r) : "f"(hi), "f"(lo));
    return r;
}
// pack a pair (a=even k lower 16, b=odd k upper 16) into hi/lo bf16x2 words
__device__ __forceinline__ void packHL(float a, float b, uint32& H, uint32& L) {
    float ha = __bfloat162float(__float2bfloat16(a));
    float hb = __bfloat162float(__float2bfloat16(b));
    H = packbf(a, b);
    L = packbf(a - ha, b - hb);
}

// ---------------- zero scratch + weight hi/lo pre-pack (one launch) ----------------
__global__ void zeroWprepKernel(const float* __restrict__ wl, const float* __restrict__ wr) {
    int i = blockIdx.x * blockDim.x + threadIdx.x;
    int stride = gridDim.x * blockDim.x;
    for (int j = i; j < Gg * Dd; j += stride) { d_s1[j] = 0.f; d_q1[j] = 0.f; d_s2[j] = 0.f; d_q2[j] = 0.f; }
    for (int j = i; j < Gg; j += stride) d_cnt[j] = 0.f;
    for (int j = i; j < Nn; j += stride) d_deg[j] = 0;
    if (i < 256 * 64) {                       // weight pack: rows 0..127 wl, 128..255 wr
        int n = i >> 6, cp = i & 63;
        const float* W = (n < 128) ? wl : wr;
        float2 v = *(const float2*)(W + (n & 127) * 128 + cp * 2);
        uint32 H, L;
        packHL(v.x, v.y, H, L);
        d_wH[i] = H;
        d_wL[i] = L;
    }
}

// ---------------- per-graph moments (batch SORTED int32; register-accumulate, boundary flush)
__global__ void momentsKernel(const float* __restrict__ xin, const int* __restrict__ batch,
                              int pass) {
    const float* x = pass ? (const float*)d_y : xin;
    float* sum = pass ? d_s2 : d_s1;
    float* sq = pass ? d_q2 : d_q1;
    int doCnt = (pass == 0);
    int lane = threadIdx.x;                       // 0..31 -> dims lane*4..lane*4+3
    int r0 = blockIdx.x * 256 + threadIdx.y * 32; // this stream's first row
    float4 a = make_float4(0.f, 0.f, 0.f, 0.f);
    float4 q = make_float4(0.f, 0.f, 0.f, 0.f);
    float c = 0.f;
    int curg = -1;

#define FLUSH_MOM()                                                             \
    {                                                                           \
        int base = curg * Dd + lane * 4;                                        \
        atomicAdd(&sum[base + 0], a.x); atomicAdd(&sum[base + 1], a.y);         \
        atomicAdd(&sum[base + 2], a.z); atomicAdd(&sum[base + 3], a.w);         \
        atomicAdd(&sq[base + 0], q.x);  atomicAdd(&sq[base + 1], q.y);          \
        atomicAdd(&sq[base + 2], q.z);  atomicAdd(&sq[base + 3], q.w);          \
        if (doCnt && lane == 0) atomicAdd(&d_cnt[curg], c);                     \
    }

    for (int i = 0; i < 32; i++) {
        int r = r0 + i;
        if (r >= Nn) break;
        int g = __ldg(&batch[r]);
        if (g != curg) {
            if (curg >= 0) FLUSH_MOM();
            curg = g;
            a = make_float4(0.f, 0.f, 0.f, 0.f);
            q = make_float4(0.f, 0.f, 0.f, 0.f);
            c = 0.f;
        }
        float4 v = ((const float4*)x)[r * 32 + lane];
        a.x += v.x; a.y += v.y; a.z += v.z; a.w += v.w;
        q.x += v.x * v.x; q.y += v.y * v.y; q.z += v.z * v.z; q.w += v.w * v.w;
        c += 1.f;
    }
    if (curg >= 0) FLUSH_MOM();
#undef FLUSH_MOM
}

// ---------------- fold moments into affine (h = A*x + C) ----------------
__global__ void statsKernel(const float* __restrict__ w, const float* __restrict__ b,
                            const float* __restrict__ ms, int pass) {
    const float* sum = pass ? d_s2 : d_s1;
    const float* sq = pass ? d_q2 : d_q1;
    float* A = pass ? d_A2 : d_A1;
    float* C = pass ? d_C2 : d_C1;
    int i = blockIdx.x * blockDim.x + threadIdx.x;
    if (i >= Gg * Dd) return;
    int g = i >> 7, dch = i & 127;
    float cnt = fmaxf(d_cnt[g], 1.f);
    float mean = sum[i] / cnt;
    float ex2 = sq[i] / cnt;
    float m = ms[dch];
    float var = ex2 - (2.f * m - m * m) * mean * mean;
    float rstd = rsqrtf(var + EPSV);
    float aa = w[dch] * rstd;
    A[i] = aa;
    C[i] = b[dch] - mean * m * aa;
}

// ---------------- apply affine per node ----------------
// pass 0: in = x, OUT = d_hH/d_hL packed bf16 ONLY (no fp32 copy).
// pass 1: in = d_y, out = dout (param).
__global__ void affineKernel(const float* __restrict__ xin, const int* __restrict__ batch,
                             float* __restrict__ dout, int pass) {
    const float* in = pass ? (const float*)d_y : xin;
    const float* A = pass ? d_A2 : d_A1;
    const float* C = pass ? d_C2 : d_C1;
    int i = blockIdx.x * blockDim.x + threadIdx.x;  // float4 index
    if (i >= Nn * 32) return;
    int r = i >> 5, col = i & 31;
    int g = __ldg(&batch[r]);
    float4 v = ((const float4*)in)[i];
    float4 a = ((const float4*)A)[g * 32 + col];
    float4 c = ((const float4*)C)[g * 32 + col];
    float4 o;
    o.x = fmaf(a.x, v.x, c.x); o.y = fmaf(a.y, v.y, c.y);
    o.z = fmaf(a.z, v.z, c.z); o.w = fmaf(a.w, v.w, c.w);
    if (pass) {
        ((float4*)dout)[i] = o;
    } else {
        uint32 H0, L0, H1, L1;
        packHL(o.x, o.y, H0, L0);
        packHL(o.z, o.w, H1, L1);
        int p = r * 64 + col * 2;   // 8B-aligned pair
        *(ull*)&d_hH[p] = ((ull)H1 << 32) | H0;
        *(ull*)&d_hL[p] = ((ull)L1 << 32) | L0;
    }
}

// ---------------- CSR build: degree -> scan -> (scan bsums inline) fixup -> scatter ----------
__global__ void degreeKernel(const int* __restrict__ ei) {
    int i = blockIdx.x * blockDim.x + threadIdx.x;
    if (i < Ee) atomicAdd(&d_deg[ei[Ee + i]], 1);
}

__global__ void scanBlocks() {  // 98 blocks x 1024 threads, exclusive scan within block
    __shared__ int wt[32];
    int i = blockIdx.x * 1024 + threadIdx.x;
    int v = (i < Nn) ? d_deg[i] : 0;
    int lane = threadIdx.x & 31, wd = threadIdx.x >> 5;
    int inc = v;
#pragma unroll
    for (int o = 1; o < 32; o <<= 1) {
        int t = __shfl_up_sync(0xffffffffu, inc, o);
        if (lane >= o) inc += t;
    }
    if (lane == 31) wt[wd] = inc;
    __syncthreads();
    if (wd == 0) {
        int t = wt[lane];
#pragma unroll
        for (int o = 1; o < 32; o <<= 1) {
            int u = __shfl_up_sync(0xffffffffu, t, o);
            if (lane >= o) t += u;
        }
        wt[lane] = t;
    }
    __syncthreads();
    int base = (wd > 0) ? wt[wd - 1] : 0;
    if (i < Nn) d_start[i] = base + inc - v;
    if (threadIdx.x == 1023) d_bsum[blockIdx.x] = base + inc;
}

// fixup with the 98-entry bsum exclusive scan done redundantly per block (removes a launch)
__global__ void fixupKernel() {
    __shared__ int pre[128];
    int t = threadIdx.x;
    int v0 = 0;
    if (t < 128) {
        v0 = (t < 98) ? d_bsum[t] : 0;
        pre[t] = v0;
    }
    __syncthreads();
    for (int o = 1; o < 128; o <<= 1) {
        int u = (t < 128 && t >= o) ? pre[t - o] : 0;
        __syncthreads();
        if (t < 128) pre[t] += u;
        __syncthreads();
    }
    if (t < 128) pre[t] -= v0;   // exclusive
    __syncthreads();
    int i = blockIdx.x * blockDim.x + t;
    if (i < Nn) {
        int st = d_start[i] + pre[i >> 10];
        d_start[i] = st;
        d_cur[i] = st;
    }
}

__global__ void scatterKernel(const int* __restrict__ ei) {
    int i = blockIdx.x * blockDim.x + threadIdx.x;
    if (i < Ee) {
        int dst = ei[Ee + i];
        int p = atomicAdd(&d_cur[dst], 1);
        d_srcs[p] = ei[i];
    }
}

// ---------------- segment-max aggregation: one warp per node ----------------
// Gathers packed bf16 hi/lo rows (d_hH/d_hL), reconstructs v = hi + lo (err 2^-17),
// max in fp32, emits packed bf16 hi/lo. fp32 h no longer exists anywhere.
__global__ void aggKernel() {
    int w = (blockIdx.x * blockDim.x + threadIdx.x) >> 5;
    int lane = threadIdx.x & 31;
    if (w >= Nn) return;
    int s = d_start[w], dg = d_deg[w];
    float4 acc = make_float4(-3.0e38f, -3.0e38f, -3.0e38f, -3.0e38f);
    for (int base = 0; base < dg; base += 32) {
        int rem = dg - base;
        if (rem > 32) rem = 32;
        int sc = (lane < rem) ? d_srcs[s + base + lane] : 0;
        for (int j = 0; j < rem; j++) {
            int scj = __shfl_sync(0xffffffffu, sc, j);
            ull h2 = __ldg(&((const ull*)d_hH)[scj * 32 + lane]);
            ull l2 = __ldg(&((const ull*)d_hL)[scj * 32 + lane]);
            uint32 ha = (uint32)h2, hb = (uint32)(h2 >> 32);
            uint32 la = (uint32)l2, lb = (uint32)(l2 >> 32);
            float v0 = __uint_as_float(ha << 16) + __uint_as_float(la << 16);
            float v1 = __uint_as_float(ha & 0xFFFF0000u) + __uint_as_float(la & 0xFFFF0000u);
            float v2 = __uint_as_float(hb << 16) + __uint_as_float(lb << 16);
            float v3 = __uint_as_float(hb & 0xFFFF0000u) + __uint_as_float(lb & 0xFFFF0000u);
            acc.x = fmaxf(acc.x, v0); acc.y = fmaxf(acc.y, v1);
            acc.z = fmaxf(acc.z, v2); acc.w = fmaxf(acc.w, v3);
        }
    }
    if (dg == 0) acc = make_float4(0.f, 0.f, 0.f, 0.f);  // PyG: empty segments -> 0
    uint32 H0, L0, H1, L1;
    packHL(acc.x, acc.y, H0, L0);
    packHL(acc.z, acc.w, H1, L1);
    int p = w * 64 + lane * 2;
    *(ull*)&d_aggH[p] = ((ull)H1 << 32) | H0;
    *(ull*)&d_aggL[p] = ((ull)L1 << 32) | L0;
}

// ================= tensor-core GEMM (bf16 split, HMMA mma.sync) — R13-proven =================
__device__ __forceinline__ void mma16816(float* c, const uint32* a, const uint32* b) {
    asm volatile(
        "mma.sync.aligned.m16n8k16.row.col.f32.bf16.bf16.f32 "
        "{%0,%1,%2,%3}, {%4,%5,%6,%7}, {%8,%9}, {%0,%1,%2,%3};"
        : "+f"(c[0]), "+f"(c[1]), "+f"(c[2]), "+f"(c[3])
        : "r"(a[0]), "r"(a[1]), "r"(a[2]), "r"(a[3]), "r"(b[0]), "r"(b[1]));
}

__global__ __launch_bounds__(256) void gemmKernel(const float* __restrict__ bl,
                                                  const float* __restrict__ x) {
    __shared__ __align__(16) uint32 aS[4096];
    __shared__ __align__(16) uint32 bS[4096];

    int tid = threadIdx.x;
    int lane = tid & 31, wid = tid >> 5;
    int warpM = wid >> 1, warpN = wid & 1;
    int r0 = blockIdx.x * 128;

    float acc[2][8][4];
#pragma unroll
    for (int mi = 0; mi < 2; mi++)
#pragma unroll
        for (int j = 0; j < 8; j++)
#pragma unroll
            for (int q = 0; q < 4; q++) acc[mi][j][q] = 0.f;

    for (int c = 0; c < 12; c++) {
        int seg = c >> 2;            // 0: hi*hi, 1: hi*lo, 2: lo*hi
        int ks0 = (c & 3) * 64;      // 0,64,128,192 within K=256
        const uint32* srcA = (seg == 2) ? ((ks0 < 128) ? d_aggL : d_hL)
                                        : ((ks0 < 128) ? d_aggH : d_hH);
        const uint32* srcW = (seg == 1) ? d_wL : d_wH;
        int kpoff = (ks0 & 127) >> 1;
        int wbase = (ks0 < 128) ? 0 : 128 * 64;

        __syncthreads();

#pragma unroll
        for (int it = 0; it < 16; it++) {
            int idx = tid + it * 256;
            int row = idx >> 5, kp = idx & 31;
            int r = r0 + row;
            uint32 pk = (r < Nn) ? __ldg(&srcA[r * 64 + kpoff + kp]) : 0u;
            int m16 = row >> 4, rr = row & 15;
            int kstep = kp >> 3, p = kp & 7;
            int t = (rr & 7) * 4 + (p & 3);
            int reg = (rr >> 3) + ((p >> 2) << 1);
            aS[((m16 * 4 + kstep) * 32 + t) * 4 + reg] = pk;
        }
#pragma unroll
        for (int it = 0; it < 16; it++) {
            int idx = tid + it * 256;
            int n = idx >> 5, kp = idx & 31;
            uint32 pk = __ldg(&srcW[wbase + n * 64 + kpoff + kp]);
            int kstep = kp >> 3, p = kp & 7;
            int n8 = n >> 3, nn = n & 7;
            int t = nn * 4 + (p & 3);
            int reg = p >> 2;
            bS[((kstep * 16 + n8) * 32 + t) * 2 + reg] = pk;
        }
        __syncthreads();

#pragma unroll
        for (int kstep = 0; kstep < 4; kstep++) {
            uint32 a[2][4];
#pragma unroll
            for (int mi = 0; mi < 2; mi++) {
                int m16 = warpM * 2 + mi;
                *(uint4*)a[mi] = *(const uint4*)&aS[((m16 * 4 + kstep) * 32 + lane) * 4];
            }
#pragma unroll
            for (int j = 0; j < 8; j++) {
                uint32 b[2];
                *(uint2*)b = *(const uint2*)&bS[((kstep * 16 + warpN * 8 + j) * 32 + lane) * 2];
                mma16816(acc[0][j], a[0], b);
                mma16816(acc[1][j], a[1], b);
            }
        }
    }

    // ---- epilogue: bias + residual + relu -> d_y ----
#pragma unroll
    for (int mi = 0; mi < 2; mi++) {
        int rbase = r0 + warpM * 32 + mi * 16 + (lane >> 2);
#pragma unroll
        for (int j = 0; j < 8; j++) {
            int nc = warpN * 64 + j * 8 + (lane & 3) * 2;
            float b0 = __ldg(&bl[nc]), b1 = __ldg(&bl[nc + 1]);
            int r = rbase;
            if (r < Nn) {
                float2 xv = *(const float2*)(x + r * 128 + nc);
                float2 o;
                o.x = fmaxf(acc[mi][j][0] + b0 + xv.x, 0.f);
                o.y = fmaxf(acc[mi][j][1] + b1 + xv.y, 0.f);
                *(float2*)(d_y + r * 128 + nc) = o;
            }
            r = rbase + 8;
            if (r < Nn) {
                float2 xv = *(const float2*)(x + r * 128 + nc);
                float2 o;
                o.x = fmaxf(acc[mi][j][2] + b0 + xv.x, 0.f);
                o.y = fmaxf(acc[mi][j][3] + b1 + xv.y, 0.f);
                *(float2*)(d_y + r * 128 + nc) = o;
            }
        }
    }
}

// ---------------- launch (capture-safe: kernel launches ONLY) ----------------
extern "C" void kernel_launch(void* const* d_in, const int* in_sizes, int n_in,
                              void* d_out, int out_size) {
    const float* x = (const float*)d_in[0];
    const int* ei = (const int*)d_in[1];      // int32 (JAX x64 disabled)
    const int* batch = (const int*)d_in[2];   // int32
    const float* n1w = (const float*)d_in[3];
    const float* n1b = (const float*)d_in[4];
    const float* n1ms = (const float*)d_in[5];
    const float* n2w = (const float*)d_in[6];
    const float* n2b = (const float*)d_in[7];
    const float* n2ms = (const float*)d_in[8];
    const float* wl = (const float*)d_in[9];
    const float* bl = (const float*)d_in[10];
    const float* wr = (const float*)d_in[11];
    float* out = (float*)d_out;

    zeroWprepKernel<<<512, 256>>>(wl, wr);
    // ---- GraphNorm 1: x -> d_hH/d_hL (packed bf16) ----
    momentsKernel<<<391, dim3(32, 8)>>>(x, batch, 0);
    statsKernel<<<128, 256>>>(n1w, n1b, n1ms, 0);
    affineKernel<<<12500, 256>>>(x, batch, out, 0);
    // ---- CSR build (by dst) ----
    degreeKernel<<<2344, 256>>>(ei);
    scanBlocks<<<98, 1024>>>();
    fixupKernel<<<391, 256>>>();
    scatterKernel<<<2344, 256>>>(ei);
    // ---- segment-max aggregation -> d_aggH/d_aggL (packed bf16) ----
    aggKernel<<<12500, 256>>>();
    // ---- fused SAGE GEMMs + bias + residual + relu -> d_y (HMMA) ----
    gemmKernel<<<782, 256>>>(bl, x);
    // ---- GraphNorm 2: d_y -> out ----
    momentsKernel<<<391, dim3(32, 8)>>>(x, batch, 1); // pass 1 reads d_y internally
    statsKernel<<<128, 256>>>(n2w, n2b, n2ms, 1);
    affineKernel<<<12500, 256>>>(x, batch, out, 1);   // pass 1 reads d_y, writes out
}

// round 15
// speedup vs baseline: 1.6227x; 1.0234x over previous
#include <cuda_runtime.h>
#include <cuda_bf16.h>

#define Nn 100000
#define Ee 600000
#define Dd 128
#define Gg 256
#define EPSV 1e-5f

typedef unsigned long long ull;
typedef unsigned int uint32;

// ---------------- scratch (device globals; no allocation allowed) ----------------
__device__ __align__(16) uint32 d_hH[Nn * 64];     // bf16x2-packed hi(h)
__device__ __align__(16) uint32 d_hL[Nn * 64];     // bf16x2-packed lo(h)
__device__ __align__(16) uint32 d_aggH[Nn * 64];   // bf16x2-packed hi(agg)
__device__ __align__(16) uint32 d_aggL[Nn * 64];   // bf16x2-packed lo(agg)
__device__ __align__(16) uint32 d_wH[256 * 64];    // bf16x2-packed hi(wl|wr)
__device__ __align__(16) uint32 d_wL[256 * 64];    // bf16x2-packed lo(wl|wr)
__device__ __align__(16) float d_y[Nn * Dd];       // relu(x + sage) pre-norm2
__device__ __align__(16) float d_s1[Gg * Dd], d_q1[Gg * Dd];
__device__ __align__(16) float d_m2[Gg * Dd * 2];  // GraphNorm-2 (sum, sumsq) interleaved
__device__ __align__(16) float d_A1[Gg * Dd], d_C1[Gg * Dd];
__device__ __align__(16) float d_A2[Gg * Dd], d_C2[Gg * Dd];
__device__ float d_cnt[Gg];
__device__ int d_deg[Nn], d_start[Nn], d_cur[Nn], d_srcs[Ee];
__device__ int d_bsum[128];

// ---------------- helpers ----------------
__device__ __forceinline__ uint32 packbf(float lo, float hi) {
    uint32 r;
    asm("cvt.rn.bf16x2.f32 %0, %1, %2;" : "=r"(r) : "f"(hi), "f"(lo));
    return r;
}
__device__ __forceinline__ void packHL(float a, float b, uint32& H, uint32& L) {
    float ha = __bfloat162float(__float2bfloat16(a));
    float hb = __bfloat162float(__float2bfloat16(b));
    H = packbf(a, b);
    L = packbf(a - ha, b - hb);
}
// no-return vector red: d_m2[(g*128+dim)*2] += s ; [..+1] += q
__device__ __forceinline__ void redMom(int g, int dim, float s, float q) {
    float* p = &d_m2[(g * 128 + dim) * 2];
    asm volatile("red.global.add.v2.f32 [%0], {%1, %2};" :: "l"(p), "f"(s), "f"(q) : "memory");
}

// ---------------- zero scratch + weight hi/lo pre-pack (one launch) ----------------
__global__ void zeroWprepKernel(const float* __restrict__ wl, const float* __restrict__ wr) {
    int i = blockIdx.x * blockDim.x + threadIdx.x;
    int stride = gridDim.x * blockDim.x;
    for (int j = i; j < Gg * Dd; j += stride) { d_s1[j] = 0.f; d_q1[j] = 0.f; }
    for (int j = i; j < Gg * Dd * 2; j += stride) d_m2[j] = 0.f;
    for (int j = i; j < Gg; j += stride) d_cnt[j] = 0.f;
    for (int j = i; j < Nn; j += stride) d_deg[j] = 0;
    if (i < 256 * 64) {                       // weight pack: rows 0..127 wl, 128..255 wr
        int n = i >> 6, cp = i & 63;
        const float* W = (n < 128) ? wl : wr;
        float2 v = *(const float2*)(W + (n & 127) * 128 + cp * 2);
        uint32 H, L;
        packHL(v.x, v.y, H, L);
        d_wH[i] = H;
        d_wL[i] = L;
    }
}

// ---------------- per-graph moments pass 0 (batch SORTED int32) ----------------
__global__ void momentsKernel(const float* __restrict__ x, const int* __restrict__ batch) {
    int lane = threadIdx.x;                       // 0..31 -> dims lane*4..lane*4+3
    int r0 = blockIdx.x * 256 + threadIdx.y * 32; // this stream's first row
    float4 a = make_float4(0.f, 0.f, 0.f, 0.f);
    float4 q = make_float4(0.f, 0.f, 0.f, 0.f);
    float c = 0.f;
    int curg = -1;

#define FLUSH_MOM()                                                             \
    {                                                                           \
        int base = curg * Dd + lane * 4;                                        \
        atomicAdd(&d_s1[base + 0], a.x); atomicAdd(&d_s1[base + 1], a.y);       \
        atomicAdd(&d_s1[base + 2], a.z); atomicAdd(&d_s1[base + 3], a.w);       \
        atomicAdd(&d_q1[base + 0], q.x); atomicAdd(&d_q1[base + 1], q.y);       \
        atomicAdd(&d_q1[base + 2], q.z); atomicAdd(&d_q1[base + 3], q.w);       \
        if (lane == 0) atomicAdd(&d_cnt[curg], c);                              \
    }

    for (int i = 0; i < 32; i++) {
        int r = r0 + i;
        if (r >= Nn) break;
        int g = __ldg(&batch[r]);
        if (g != curg) {
            if (curg >= 0) FLUSH_MOM();
            curg = g;
            a = make_float4(0.f, 0.f, 0.f, 0.f);
            q = make_float4(0.f, 0.f, 0.f, 0.f);
            c = 0.f;
        }
        float4 v = ((const float4*)x)[r * 32 + lane];
        a.x += v.x; a.y += v.y; a.z += v.z; a.w += v.w;
        q.x += v.x * v.x; q.y += v.y * v.y; q.z += v.z * v.z; q.w += v.w * v.w;
        c += 1.f;
    }
    if (curg >= 0) FLUSH_MOM();
#undef FLUSH_MOM
}

// ---------------- fold moments into affine (h = A*x + C) ----------------
// pass 0 reads d_s1/d_q1; pass 1 reads interleaved d_m2.
__global__ void statsKernel(const float* __restrict__ w, const float* __restrict__ b,
                            const float* __restrict__ ms, int pass) {
    float* A = pass ? d_A2 : d_A1;
    float* C = pass ? d_C2 : d_C1;
    int i = blockIdx.x * blockDim.x + threadIdx.x;
    if (i >= Gg * Dd) return;
    int g = i >> 7, dch = i & 127;
    float cnt = fmaxf(d_cnt[g], 1.f);
    float sv, qv;
    if (pass) { sv = d_m2[i * 2]; qv = d_m2[i * 2 + 1]; }
    else { sv = d_s1[i]; qv = d_q1[i]; }
    float mean = sv / cnt;
    float ex2 = qv / cnt;
    float m = ms[dch];
    float var = ex2 - (2.f * m - m * m) * mean * mean;
    float rstd = rsqrtf(var + EPSV);
    float aa = w[dch] * rstd;
    A[i] = aa;
    C[i] = b[dch] - mean * m * aa;
}

// ---------------- apply affine per node ----------------
// pass 0: in = x, OUT = d_hH/d_hL packed bf16. pass 1: in = d_y, out = dout.
__global__ void affineKernel(const float* __restrict__ xin, const int* __restrict__ batch,
                             float* __restrict__ dout, int pass) {
    const float* in = pass ? (const float*)d_y : xin;
    const float* A = pass ? d_A2 : d_A1;
    const float* C = pass ? d_C2 : d_C1;
    int i = blockIdx.x * blockDim.x + threadIdx.x;  // float4 index
    if (i >= Nn * 32) return;
    int r = i >> 5, col = i & 31;
    int g = __ldg(&batch[r]);
    float4 v = ((const float4*)in)[i];
    float4 a = ((const float4*)A)[g * 32 + col];
    float4 c = ((const float4*)C)[g * 32 + col];
    float4 o;
    o.x = fmaf(a.x, v.x, c.x); o.y = fmaf(a.y, v.y, c.y);
    o.z = fmaf(a.z, v.z, c.z); o.w = fmaf(a.w, v.w, c.w);
    if (pass) {
        ((float4*)dout)[i] = o;
    } else {
        uint32 H0, L0, H1, L1;
        packHL(o.x, o.y, H0, L0);
        packHL(o.z, o.w, H1, L1);
        int p = r * 64 + col * 2;
        *(ull*)&d_hH[p] = ((ull)H1 << 32) | H0;
        *(ull*)&d_hL[p] = ((ull)L1 << 32) | L0;
    }
}

// ---------------- CSR build: degree -> scan -> fixup(inline bsum scan) -> scatter --------
__global__ void degreeKernel(const int* __restrict__ ei) {
    int i = blockIdx.x * blockDim.x + threadIdx.x;
    if (i < Ee) atomicAdd(&d_deg[ei[Ee + i]], 1);
}

__global__ void scanBlocks() {  // 98 blocks x 1024 threads, exclusive scan within block
    __shared__ int wt[32];
    int i = blockIdx.x * 1024 + threadIdx.x;
    int v = (i < Nn) ? d_deg[i] : 0;
    int lane = threadIdx.x & 31, wd = threadIdx.x >> 5;
    int inc = v;
#pragma unroll
    for (int o = 1; o < 32; o <<= 1) {
        int t = __shfl_up_sync(0xffffffffu, inc, o);
        if (lane >= o) inc += t;
    }
    if (lane == 31) wt[wd] = inc;
    __syncthreads();
    if (wd == 0) {
        int t = wt[lane];
#pragma unroll
        for (int o = 1; o < 32; o <<= 1) {
            int u = __shfl_up_sync(0xffffffffu, t, o);
            if (lane >= o) t += u;
        }
        wt[lane] = t;
    }
    __syncthreads();
    int base = (wd > 0) ? wt[wd - 1] : 0;
    if (i < Nn) d_start[i] = base + inc - v;
    if (threadIdx.x == 1023) d_bsum[blockIdx.x] = base + inc;
}

__global__ void fixupKernel() {
    __shared__ int pre[128];
    int t = threadIdx.x;
    int v0 = 0;
    if (t < 128) {
        v0 = (t < 98) ? d_bsum[t] : 0;
        pre[t] = v0;
    }
    __syncthreads();
    for (int o = 1; o < 128; o <<= 1) {
        int u = (t < 128 && t >= o) ? pre[t - o] : 0;
        __syncthreads();
        if (t < 128) pre[t] += u;
        __syncthreads();
    }
    if (t < 128) pre[t] -= v0;   // exclusive
    __syncthreads();
    int i = blockIdx.x * blockDim.x + t;
    if (i < Nn) {
        int st = d_start[i] + pre[i >> 10];
        d_start[i] = st;
        d_cur[i] = st;
    }
}

__global__ void scatterKernel(const int* __restrict__ ei) {
    int i = blockIdx.x * blockDim.x + threadIdx.x;
    if (i < Ee) {
        int dst = ei[Ee + i];
        int p = atomicAdd(&d_cur[dst], 1);
        d_srcs[p] = ei[i];
    }
}

// ---------------- segment-max aggregation: one warp per node ----------------
__global__ void aggKernel() {
    int w = (blockIdx.x * blockDim.x + threadIdx.x) >> 5;
    int lane = threadIdx.x & 31;
    if (w >= Nn) return;
    int s = d_start[w], dg = d_deg[w];
    float4 acc = make_float4(-3.0e38f, -3.0e38f, -3.0e38f, -3.0e38f);
    for (int base = 0; base < dg; base += 32) {
        int rem = dg - base;
        if (rem > 32) rem = 32;
        int sc = (lane < rem) ? d_srcs[s + base + lane] : 0;
        for (int j = 0; j < rem; j++) {
            int scj = __shfl_sync(0xffffffffu, sc, j);
            ull h2 = __ldg(&((const ull*)d_hH)[scj * 32 + lane]);
            ull l2 = __ldg(&((const ull*)d_hL)[scj * 32 + lane]);
            uint32 ha = (uint32)h2, hb = (uint32)(h2 >> 32);
            uint32 la = (uint32)l2, lb = (uint32)(l2 >> 32);
            float v0 = __uint_as_float(ha << 16) + __uint_as_float(la << 16);
            float v1 = __uint_as_float(ha & 0xFFFF0000u) + __uint_as_float(la & 0xFFFF0000u);
            float v2 = __uint_as_float(hb << 16) + __uint_as_float(lb << 16);
            float v3 = __uint_as_float(hb & 0xFFFF0000u) + __uint_as_float(lb & 0xFFFF0000u);
            acc.x = fmaxf(acc.x, v0); acc.y = fmaxf(acc.y, v1);
            acc.z = fmaxf(acc.z, v2); acc.w = fmaxf(acc.w, v3);
        }
    }
    if (dg == 0) acc = make_float4(0.f, 0.f, 0.f, 0.f);  // PyG: empty segments -> 0
    uint32 H0, L0, H1, L1;
    packHL(acc.x, acc.y, H0, L0);
    packHL(acc.z, acc.w, H1, L1);
    int p = w * 64 + lane * 2;
    *(ull*)&d_aggH[p] = ((ull)H1 << 32) | H0;
    *(ull*)&d_aggL[p] = ((ull)L1 << 32) | L0;
}

// ================= tensor-core GEMM (bf16 split, HMMA) + fused GraphNorm-2 moments ========
__device__ __forceinline__ void mma16816(float* c, const uint32* a, const uint32* b) {
    asm volatile(
        "mma.sync.aligned.m16n8k16.row.col.f32.bf16.bf16.f32 "
        "{%0,%1,%2,%3}, {%4,%5,%6,%7}, {%8,%9}, {%0,%1,%2,%3};"
        : "+f"(c[0]), "+f"(c[1]), "+f"(c[2]), "+f"(c[3])
        : "r"(a[0]), "r"(a[1]), "r"(a[2]), "r"(a[3]), "r"(b[0]), "r"(b[1]));
}

__global__ __launch_bounds__(256) void gemmKernel(const float* __restrict__ bl,
                                                  const float* __restrict__ x,
                                                  const int* __restrict__ batch) {
    __shared__ __align__(16) uint32 aS[4096];
    __shared__ __align__(16) uint32 bS[4096];

    int tid = threadIdx.x;
    int lane = tid & 31, wid = tid >> 5;
    int warpM = wid >> 1, warpN = wid & 1;
    int r0 = blockIdx.x * 128;

    float acc[2][8][4];
#pragma unroll
    for (int mi = 0; mi < 2; mi++)
#pragma unroll
        for (int j = 0; j < 8; j++)
#pragma unroll
            for (int q = 0; q < 4; q++) acc[mi][j][q] = 0.f;

    for (int c = 0; c < 12; c++) {
        int seg = c >> 2;            // 0: hi*hi, 1: hi*lo, 2: lo*hi
        int ks0 = (c & 3) * 64;      // 0,64,128,192 within K=256
        const uint32* srcA = (seg == 2) ? ((ks0 < 128) ? d_aggL : d_hL)
                                        : ((ks0 < 128) ? d_aggH : d_hH);
        const uint32* srcW = (seg == 1) ? d_wL : d_wH;
        int kpoff = (ks0 & 127) >> 1;
        int wbase = (ks0 < 128) ? 0 : 128 * 64;

        __syncthreads();

#pragma unroll
        for (int it = 0; it < 16; it++) {
            int idx = tid + it * 256;
            int row = idx >> 5, kp = idx & 31;
            int r = r0 + row;
            uint32 pk = (r < Nn) ? __ldg(&srcA[r * 64 + kpoff + kp]) : 0u;
            int m16 = row >> 4, rr = row & 15;
            int kstep = kp >> 3, p = kp & 7;
            int t = (rr & 7) * 4 + (p & 3);
            int reg = (rr >> 3) + ((p >> 2) << 1);
            aS[((m16 * 4 + kstep) * 32 + t) * 4 + reg] = pk;
        }
#pragma unroll
        for (int it = 0; it < 16; it++) {
            int idx = tid + it * 256;
            int n = idx >> 5, kp = idx & 31;
            uint32 pk = __ldg(&srcW[wbase + n * 64 + kpoff + kp]);
            int kstep = kp >> 3, p = kp & 7;
            int n8 = n >> 3, nn = n & 7;
            int t = nn * 4 + (p & 3);
            int reg = p >> 2;
            bS[((kstep * 16 + n8) * 32 + t) * 2 + reg] = pk;
        }
        __syncthreads();

#pragma unroll
        for (int kstep = 0; kstep < 4; kstep++) {
            uint32 a[2][4];
#pragma unroll
            for (int mi = 0; mi < 2; mi++) {
                int m16 = warpM * 2 + mi;
                *(uint4*)a[mi] = *(const uint4*)&aS[((m16 * 4 + kstep) * 32 + lane) * 4];
            }
#pragma unroll
            for (int j = 0; j < 8; j++) {
                uint32 b[2];
                *(uint2*)b = *(const uint2*)&bS[((kstep * 16 + warpN * 8 + j) * 32 + lane) * 2];
                mma16816(acc[0][j], a[0], b);
                mma16816(acc[1][j], a[1], b);
            }
        }
    }

    // ---- epilogue: bias + residual + relu -> d_y, fused GraphNorm-2 moment REDG ----
    // Thread rows: rA + {0,8,16,24} (ascending), rv = (mi, half) -> acc[mi][j][half*2+..]
    int rA = r0 + warpM * 32 + (lane >> 2);
    int gr[4];
    bool ok[4];
#pragma unroll
    for (int v = 0; v < 4; v++) {
        int r = rA + v * 8;
        ok[v] = (r < Nn);
        gr[v] = ok[v] ? __ldg(&batch[r]) : -1;
    }

#pragma unroll
    for (int j = 0; j < 8; j++) {
        int nc = warpN * 64 + j * 8 + (lane & 3) * 2;
        float b0 = __ldg(&bl[nc]), b1 = __ldg(&bl[nc + 1]);
        float s0 = 0.f, s1 = 0.f, q0 = 0.f, q1 = 0.f;
        int curG = -1;
#pragma unroll
        for (int v = 0; v < 4; v++) {       // v = mi*2 + half; row = rA + v*8
            if (!ok[v]) continue;
            int mi = v >> 1, half = v & 1;
            int r = rA + v * 8;
            float2 xv = *(const float2*)(x + r * 128 + nc);
            float y0 = fmaxf(acc[mi][j][half * 2 + 0] + b0 + xv.x, 0.f);
            float y1 = fmaxf(acc[mi][j][half * 2 + 1] + b1 + xv.y, 0.f);
            *(float2*)(d_y + r * 128 + nc) = make_float2(y0, y1);
            if (gr[v] != curG) {
                if (curG >= 0) { redMom(curG, nc, s0, q0); redMom(curG, nc + 1, s1, q1); }
                curG = gr[v];
                s0 = s1 = q0 = q1 = 0.f;
            }
            s0 += y0; q0 += y0 * y0;
            s1 += y1; q1 += y1 * y1;
        }
        if (curG >= 0) { redMom(curG, nc, s0, q0); redMom(curG, nc + 1, s1, q1); }
    }
}

// ---------------- launch (capture-safe: kernel launches ONLY) ----------------
extern "C" void kernel_launch(void* const* d_in, const int* in_sizes, int n_in,
                              void* d_out, int out_size) {
    const float* x = (const float*)d_in[0];
    const int* ei = (const int*)d_in[1];      // int32 (JAX x64 disabled)
    const int* batch = (const int*)d_in[2];   // int32
    const float* n1w = (const float*)d_in[3];
    const float* n1b = (const float*)d_in[4];
    const float* n1ms = (const float*)d_in[5];
    const float* n2w = (const float*)d_in[6];
    const float* n2b = (const float*)d_in[7];
    const float* n2ms = (const float*)d_in[8];
    const float* wl = (const float*)d_in[9];
    const float* bl = (const float*)d_in[10];
    const float* wr = (const float*)d_in[11];
    float* out = (float*)d_out;

    zeroWprepKernel<<<512, 256>>>(wl, wr);
    // ---- GraphNorm 1: x -> d_hH/d_hL (packed bf16) ----
    momentsKernel<<<391, dim3(32, 8)>>>(x, batch);
    statsKernel<<<128, 256>>>(n1w, n1b, n1ms, 0);
    affineKernel<<<12500, 256>>>(x, batch, out, 0);
    // ---- CSR build (by dst) ----
    degreeKernel<<<2344, 256>>>(ei);
    scanBlocks<<<98, 1024>>>();
    fixupKernel<<<391, 256>>>();
    scatterKernel<<<2344, 256>>>(ei);
    // ---- segment-max aggregation -> d_aggH/d_aggL (packed bf16) ----
    aggKernel<<<12500, 256>>>();
    // ---- SAGE GEMMs + bias + residual + relu -> d_y, + fused GraphNorm-2 moments ----
    gemmKernel<<<782, 256>>>(bl, x, batch);
    // ---- GraphNorm 2 finish: stats + affine (d_y -> out) ----
    statsKernel<<<128, 256>>>(n2w, n2b, n2ms, 1);
    affineKernel<<<12500, 256>>>(x, batch, out, 1);
}